// round 11
// baseline (speedup 1.0000x reference)
#include <cuda_runtime.h>
#include <cuda_bf16.h>
#include <math.h>
#include <stdint.h>

// ---------------------------------------------------------------------------
// AttentiveFPConv: out = tanh(x@Wn + bn + aggr@Wg + bg)
//   aggr[u] = sum_{e: row[e]==u} g[col[e]],  g[v] = x[v] * sigmoid((x@Wa+ba)[v])
// N = 40000, E = 640000, D = 128.
// out = tanh([x | aggr] @ [Wn ; Wg] + (bn+bg))  -- one K=256 GEMM.
// GEMMs: mma.sync m16n8k16 bf16, hi/lo split (3 terms), fp32 accum,
//        K-split SMEM (72KB) for 2 CTAs/SM, fast-math epilogue.
// Aggregation: CSR build + MLP-4 warp-per-node gather (no atomics on data;
//              LTS atomic-ALU was the bound for the RED scatter).
// ---------------------------------------------------------------------------

#define NODES_MAX 40000
#define EDGES_MAX 640000
#define DIM 128

__device__ float g_ga[NODES_MAX * DIM];
__device__ float g_aggr[NODES_MAX * DIM];
__device__ int2  g_eidx[EDGES_MAX];
__device__ int   g_ecol[EDGES_MAX];
__device__ int   g_deg[NODES_MAX + 1];
__device__ int   g_off[NODES_MAX + 1];
__device__ int   g_cursor[NODES_MAX];
__device__ int   g_is64;
__device__ float g_bsum[DIM];
__device__ __align__(16) __nv_bfloat16 g_wconv[3][2][DIM * DIM];

// ---------------------------------------------------------------------------
__device__ __forceinline__ uint32_t smem_u32(const void* p) {
    uint32_t a;
    asm("{ .reg .u64 t; cvta.to.shared.u64 t, %1; cvt.u32.u64 %0, t; }" : "=r"(a) : "l"(p));
    return a;
}
__device__ __forceinline__ void ldsm4(uint32_t a, uint32_t& r0, uint32_t& r1,
                                      uint32_t& r2, uint32_t& r3) {
    asm volatile("ldmatrix.sync.aligned.m8n8.x4.shared.b16 {%0,%1,%2,%3}, [%4];"
                 : "=r"(r0), "=r"(r1), "=r"(r2), "=r"(r3) : "r"(a));
}
__device__ __forceinline__ void mma16816(float* c, uint32_t a0, uint32_t a1,
                                         uint32_t a2, uint32_t a3,
                                         uint32_t b0, uint32_t b1) {
    asm volatile(
        "mma.sync.aligned.m16n8k16.row.col.f32.bf16.bf16.f32 "
        "{%0,%1,%2,%3}, {%4,%5,%6,%7}, {%8,%9}, {%0,%1,%2,%3};"
        : "+f"(c[0]), "+f"(c[1]), "+f"(c[2]), "+f"(c[3])
        : "r"(a0), "r"(a1), "r"(a2), "r"(a3), "r"(b0), "r"(b1));
}
__device__ __forceinline__ uint32_t pack_bf16x2(float x, float y) {
    __nv_bfloat16 hx = __float2bfloat16(x), hy = __float2bfloat16(y);
    return (uint32_t)*(unsigned short*)&hx | ((uint32_t)*(unsigned short*)&hy << 16);
}
__device__ __forceinline__ float sigmoid_fast(float x) {
    float e = __expf(-x);
    return __fdividef(1.f, 1.f + e);
}
__device__ __forceinline__ float tanh_fast(float x) {
    float e = __expf(-2.f * x);
    return (1.f - e) * __fdividef(1.f, 1.f + e);
}

// ---------------------------------------------------------------------------
__global__ void detect_idx_kernel(const int* __restrict__ ei32) {
    if (threadIdx.x == 0 && blockIdx.x == 0) {
        int is64 = 1;
        #pragma unroll
        for (int i = 0; i < 32; i++)
            if (ei32[2 * i + 1] != 0) { is64 = 0; break; }
        g_is64 = is64;
    }
}

// zero degree counters + bias sum
__global__ __launch_bounds__(256) void zero_deg_bsum_kernel(
    int N, const float* __restrict__ bn, const float* __restrict__ bg)
{
    int i = blockIdx.x * blockDim.x + threadIdx.x;
    if (i <= N) g_deg[i] = 0;
    if (i < DIM) g_bsum[i] = bn[i] + bg[i];
}

// Pack (row,col) AND histogram rows in one pass.
__global__ __launch_bounds__(256) void pack_hist_kernel(const void* __restrict__ ei, int E) {
    int e = blockIdx.x * blockDim.x + threadIdx.x;
    if (e >= E) return;
    int row, col;
    if (g_is64) {
        const long long* p = (const long long*)ei;
        row = (int)p[e]; col = (int)p[E + e];
    } else {
        const int* p = (const int*)ei;
        row = p[e]; col = p[E + e];
    }
    g_eidx[e] = make_int2(row, col);
    atomicAdd(&g_deg[row], 1);
}

// Single-block exclusive scan of g_deg -> g_off (+ cursor copy).
__global__ __launch_bounds__(1024) void scan_kernel(int N) {
    __shared__ int part[1024];
    int t = threadIdx.x;
    int chunk = (N + 1023) / 1024;
    int start = t * chunk;
    int end = min(start + chunk, N);
    int s = 0;
    for (int i = start; i < end; i++) s += g_deg[i];
    part[t] = s;
    __syncthreads();
    #pragma unroll
    for (int d = 1; d < 1024; d <<= 1) {
        int v = (t >= d) ? part[t - d] : 0;
        __syncthreads();
        part[t] += v;
        __syncthreads();
    }
    int excl = (t == 0) ? 0 : part[t - 1];
    for (int i = start; i < end; i++) {
        int dg = g_deg[i];
        g_off[i] = excl;
        g_cursor[i] = excl;
        excl += dg;
    }
    if (t == 1023) g_off[N] = excl;
}

__global__ __launch_bounds__(256) void fill_csr_kernel(int E) {
    int e = blockIdx.x * blockDim.x + threadIdx.x;
    if (e >= E) return;
    int2 rc = g_eidx[e];
    int pos = atomicAdd(&g_cursor[rc.x], 1);
    g_ecol[pos] = rc.y;
}

// Warp-per-node gather with MLP=4: 4 independent accumulators + 4 in-flight
// LDG.128 per iteration. aggr[u] = sum g[ecol[i]], writes every row (zeros
// for degree-0 nodes) -> no zero_aggr kernel needed.
__global__ __launch_bounds__(256) void spmm_kernel(int N) {
    int warp = (int)((blockIdx.x * 256 + threadIdx.x) >> 5);
    if (warp >= N) return;
    int lane = threadIdx.x & 31;
    int beg = g_off[warp], end = g_off[warp + 1];

    float4 a0 = make_float4(0.f, 0.f, 0.f, 0.f);
    float4 a1 = a0, a2 = a0, a3 = a0;

    int j = beg;
    for (; j + 4 <= end; j += 4) {
        int c0 = g_ecol[j + 0];
        int c1 = g_ecol[j + 1];
        int c2 = g_ecol[j + 2];
        int c3 = g_ecol[j + 3];
        float4 v0 = *((const float4*)(g_ga + (size_t)c0 * DIM) + lane);
        float4 v1 = *((const float4*)(g_ga + (size_t)c1 * DIM) + lane);
        float4 v2 = *((const float4*)(g_ga + (size_t)c2 * DIM) + lane);
        float4 v3 = *((const float4*)(g_ga + (size_t)c3 * DIM) + lane);
        a0.x += v0.x; a0.y += v0.y; a0.z += v0.z; a0.w += v0.w;
        a1.x += v1.x; a1.y += v1.y; a1.z += v1.z; a1.w += v1.w;
        a2.x += v2.x; a2.y += v2.y; a2.z += v2.z; a2.w += v2.w;
        a3.x += v3.x; a3.y += v3.y; a3.z += v3.z; a3.w += v3.w;
    }
    for (; j < end; j++) {
        int c = g_ecol[j];
        float4 v = *((const float4*)(g_ga + (size_t)c * DIM) + lane);
        a0.x += v.x; a0.y += v.y; a0.z += v.z; a0.w += v.w;
    }
    float4 r;
    r.x = (a0.x + a1.x) + (a2.x + a3.x);
    r.y = (a0.y + a1.y) + (a2.y + a3.y);
    r.z = (a0.z + a1.z) + (a2.z + a3.z);
    r.w = (a0.w + a1.w) + (a2.w + a3.w);
    *((float4*)(g_aggr + (size_t)warp * DIM) + lane) = r;
}

// prep weights: W[k][n] -> Bt[n][k] hi/lo bf16, coalesced via smem transpose.
__global__ __launch_bounds__(256) void prep_weights_kernel(
    const float* __restrict__ Wn, const float* __restrict__ Wg,
    const float* __restrict__ Wa)
{
    int mat = blockIdx.x >> 3;
    int kc  = (blockIdx.x & 7) * 16;
    const float* W = mat == 0 ? Wn : (mat == 1 ? Wg : Wa);
    __shared__ float tile[16][DIM];
    for (int i = threadIdx.x; i < 16 * DIM; i += 256) {
        int kk = i >> 7, n = i & 127;
        tile[kk][n] = W[(size_t)(kc + kk) * DIM + n];
    }
    __syncthreads();
    uint32_t* hi = (uint32_t*)g_wconv[mat][0];
    uint32_t* lo = (uint32_t*)g_wconv[mat][1];
    for (int i = threadIdx.x; i < DIM * 8; i += 256) {
        int n = i >> 3, kp = (i & 7) * 2;
        float v0 = tile[kp][n], v1 = tile[kp + 1][n];
        float h0 = __bfloat162float(__float2bfloat16(v0));
        float h1 = __bfloat162float(__float2bfloat16(v1));
        int idx = (n * DIM + kc + kp) >> 1;
        hi[idx] = pack_bf16x2(h0, h1);
        lo[idx] = pack_bf16x2(v0 - h0, v1 - h1);
    }
}

// ---------------------------------------------------------------------------
// mma.sync GEMM over nh half-K passes of 64. Half h reads A = (h<2?A0:A1)
// at k-offset (h&1)*64, weights g_wconv[(h<2?w0:w1)] at the same k-offset.
//   mode 1: out = extra * sigmoid(acc + bias)
//   mode 3: out = tanh(acc + bias)
// CTA 128x128 tile, 8 warps 4(M)x2(N), SMEM 72KB -> 2 CTAs/SM.
// ---------------------------------------------------------------------------
#define KH 64
#define BSTRIDE 144
#define HBUF (DIM * BSTRIDE)           // 18432
#define SM_TOTAL (4 * HBUF)            // 73728

__global__ __launch_bounds__(256, 2) void gemm_mma_fused(
    const float* __restrict__ A0, const float* __restrict__ A1,
    int w0, int w1, int nh,
    const float* __restrict__ bias, const float* __restrict__ extra,
    float* __restrict__ out, int N, int mode)
{
    extern __shared__ __align__(16) char smem[];
    const uint32_t sb  = smem_u32(smem);
    const uint32_t sAH = sb, sAL = sb + HBUF, sBH = sb + 2 * HBUF, sBL = sb + 3 * HBUF;
    const int tid = threadIdx.x, lane = tid & 31, wid = tid >> 5;
    const int m0 = blockIdx.x * 128;
    const int wm = wid & 3;
    const int wn = wid >> 2;

    float acc[2][8][4];
    #pragma unroll
    for (int mt = 0; mt < 2; mt++)
        #pragma unroll
        for (int nt = 0; nt < 8; nt++)
            #pragma unroll
            for (int q = 0; q < 4; q++) acc[mt][nt][q] = 0.f;

    #pragma unroll 1
    for (int h = 0; h < nh; h++) {
        if (h) __syncthreads();

        const float* A = (h < 2) ? A0 : A1;
        const int widx = (h < 2) ? w0 : w1;
        const int kh = (h & 1);

        // A half: 128 rows x 64 cols fp32, split hi/lo bf16
        for (int i = tid; i < 128 * 16; i += 256) {
            int rl = i >> 4;
            int c4 = (i & 15) * 4;
            int r = m0 + rl; if (r >= N) r = N - 1;
            float4 v = *(const float4*)(A + (size_t)r * DIM + kh * KH + c4);
            float h0 = __bfloat162float(__float2bfloat16(v.x));
            float h1 = __bfloat162float(__float2bfloat16(v.y));
            float h2 = __bfloat162float(__float2bfloat16(v.z));
            float h3 = __bfloat162float(__float2bfloat16(v.w));
            int off = rl * BSTRIDE + c4 * 2;
            *(uint2*)(smem + off) =
                make_uint2(pack_bf16x2(h0, h1), pack_bf16x2(h2, h3));
            *(uint2*)(smem + HBUF + off) =
                make_uint2(pack_bf16x2(v.x - h0, v.y - h1),
                           pack_bf16x2(v.z - h2, v.w - h3));
        }
        // B half: pre-split Bt[n][k], 8 x 16B per row, hi and lo buffers
        {
            const char* wh = (const char*)g_wconv[widx][0];
            const char* wl = (const char*)g_wconv[widx][1];
            for (int i = tid; i < 2048; i += 256) {
                int buf = i >> 10;
                int idx = i & 1023;
                int r = idx >> 3, c = (idx & 7) * 16;
                const char* src = (buf ? wl : wh) + (size_t)r * 256 + kh * 128 + c;
                char* dst = smem + (buf ? 3 : 2) * HBUF + r * BSTRIDE + c;
                *(uint4*)dst = *(const uint4*)src;
            }
        }
        __syncthreads();

        #pragma unroll
        for (int s = 0; s < 4; s++) {
            const int k0 = s * 16;
            uint32_t ah[2][4], al[2][4];
            #pragma unroll
            for (int mt = 0; mt < 2; mt++) {
                int row = wm * 32 + mt * 16 + (lane & 15);
                int col = k0 + (lane >> 4) * 8;
                uint32_t off = row * BSTRIDE + col * 2;
                ldsm4(sAH + off, ah[mt][0], ah[mt][1], ah[mt][2], ah[mt][3]);
                ldsm4(sAL + off, al[mt][0], al[mt][1], al[mt][2], al[mt][3]);
            }
            #pragma unroll
            for (int np = 0; np < 4; np++) {
                uint32_t bh[2][2], bl[2][2];
                int g = lane >> 3;
                int row = wn * 64 + np * 16 + (g >> 1) * 8 + (lane & 7);
                int col = k0 + (g & 1) * 8;
                uint32_t off = row * BSTRIDE + col * 2;
                ldsm4(sBH + off, bh[0][0], bh[0][1], bh[1][0], bh[1][1]);
                ldsm4(sBL + off, bl[0][0], bl[0][1], bl[1][0], bl[1][1]);
                #pragma unroll
                for (int mt = 0; mt < 2; mt++)
                    #pragma unroll
                    for (int j = 0; j < 2; j++) {
                        int nt = 2 * np + j;
                        mma16816(acc[mt][nt], ah[mt][0], ah[mt][1], ah[mt][2], ah[mt][3],
                                 bh[j][0], bh[j][1]);
                        mma16816(acc[mt][nt], ah[mt][0], ah[mt][1], ah[mt][2], ah[mt][3],
                                 bl[j][0], bl[j][1]);
                        mma16816(acc[mt][nt], al[mt][0], al[mt][1], al[mt][2], al[mt][3],
                                 bh[j][0], bh[j][1]);
                    }
            }
        }
    }

    // --- Epilogue ---
    float2 bb[8];
    #pragma unroll
    for (int nt = 0; nt < 8; nt++) {
        int n = wn * 64 + nt * 8 + 2 * (lane & 3);
        bb[nt] = *(const float2*)(bias + n);
    }
    #pragma unroll
    for (int mt = 0; mt < 2; mt++) {
        #pragma unroll
        for (int half = 0; half < 2; half++) {
            int m = m0 + wm * 32 + mt * 16 + (lane >> 2) + half * 8;
            if (m >= N) continue;
            #pragma unroll
            for (int nt = 0; nt < 8; nt++) {
                int n = wn * 64 + nt * 8 + 2 * (lane & 3);
                float rx = acc[mt][nt][half * 2 + 0] + bb[nt].x;
                float ry = acc[mt][nt][half * 2 + 1] + bb[nt].y;
                if (mode == 1) {
                    float2 xv = *(const float2*)(extra + (size_t)m * DIM + n);
                    rx = xv.x * sigmoid_fast(rx);
                    ry = xv.y * sigmoid_fast(ry);
                } else {   // mode 3
                    rx = tanh_fast(rx);
                    ry = tanh_fast(ry);
                }
                *(float2*)(out + (size_t)m * DIM + n) = make_float2(rx, ry);
            }
        }
    }
}

// ---------------------------------------------------------------------------
extern "C" void kernel_launch(void* const* d_in, const int* in_sizes, int n_in,
                              void* d_out, int out_size)
{
    const float* x    = (const float*)d_in[0];
    const void*  ei   = d_in[1];
    const float* Wn_w = (const float*)d_in[2];
    const float* Wn_b = (const float*)d_in[3];
    const float* Wg_w = (const float*)d_in[4];
    const float* Wg_b = (const float*)d_in[5];
    const float* Wa_w = (const float*)d_in[6];
    const float* Wa_b = (const float*)d_in[7];
    float* out = (float*)d_out;

    const int N = in_sizes[0] / DIM;
    const int E = in_sizes[1] / 2;

    float *p_ga, *p_aggr, *p_bsum;
    cudaGetSymbolAddress((void**)&p_ga,   g_ga);
    cudaGetSymbolAddress((void**)&p_aggr, g_aggr);
    cudaGetSymbolAddress((void**)&p_bsum, g_bsum);

    cudaFuncSetAttribute(gemm_mma_fused,
                         cudaFuncAttributeMaxDynamicSharedMemorySize, SM_TOTAL);

    prep_weights_kernel<<<24, 256>>>(Wn_w, Wg_w, Wa_w);
    detect_idx_kernel<<<1, 32>>>((const int*)ei);
    zero_deg_bsum_kernel<<<(N + 256) / 256, 256>>>(N, Wn_b, Wg_b);
    pack_hist_kernel<<<(E + 255) / 256, 256>>>(ei, E);
    scan_kernel<<<1, 1024>>>(N);
    fill_csr_kernel<<<(E + 255) / 256, 256>>>(E);

    int gblocks = (N + 127) / 128;
    // g = x * sigmoid(x@Wa + ba)
    gemm_mma_fused<<<gblocks, 256, SM_TOTAL>>>(x, nullptr, 2, 2, 2,
                                               Wa_b, x, p_ga, N, 1);
    // aggr = CSR gather of g (no atomics)
    {
        long long threads = (long long)N * 32;
        int blocks = (int)((threads + 255) / 256);
        spmm_kernel<<<blocks, 256>>>(N);
    }
    // out = tanh([x | aggr] @ [Wn ; Wg] + bn + bg)   (K=256, 4 halves)
    gemm_mma_fused<<<gblocks, 256, SM_TOTAL>>>(x, p_aggr, 0, 1, 4,
                                               p_bsum, nullptr, out, N, 3);
}

// round 12
// speedup vs baseline: 1.2576x; 1.2576x over previous
#include <cuda_runtime.h>
#include <cuda_bf16.h>
#include <math.h>
#include <stdint.h>

// ---------------------------------------------------------------------------
// AttentiveFPConv: out = tanh(x@Wn + bn + aggr@Wg + bg)
//   aggr[u] = sum_{e: row[e]==u} g[col[e]],  g[v] = x[v] * sigmoid((x@Wa+ba)[v])
// N = 40000, E = 640000, D = 128.
// GEMMs: mma.sync m16n8k16 bf16, hi/lo split (3 terms), fp32 accum,
//        K-split SMEM (72KB) for 2 CTAs/SM, fast-math epilogue.
// Aggregation: warp-per-edge red.global.add.v4.f32 (LTS-bandwidth-bound).
// Overlap: y_n = x@Wn+bn runs on a side stream CONCURRENT with the scatter
//          (scatter is LTS-bound, GEMM is tensor-bound - complementary).
// ---------------------------------------------------------------------------

#define NODES_MAX 40000
#define EDGES_MAX 640000
#define DIM 128

__device__ float g_yn[NODES_MAX * DIM];
__device__ float g_ga[NODES_MAX * DIM];
__device__ float g_aggr[NODES_MAX * DIM];
__device__ int2  g_eidx[EDGES_MAX];
__device__ int   g_is64;
__device__ __align__(16) __nv_bfloat16 g_wconv[3][2][DIM * DIM];

// ---------------------------------------------------------------------------
__device__ __forceinline__ uint32_t smem_u32(const void* p) {
    uint32_t a;
    asm("{ .reg .u64 t; cvta.to.shared.u64 t, %1; cvt.u32.u64 %0, t; }" : "=r"(a) : "l"(p));
    return a;
}
__device__ __forceinline__ void ldsm4(uint32_t a, uint32_t& r0, uint32_t& r1,
                                      uint32_t& r2, uint32_t& r3) {
    asm volatile("ldmatrix.sync.aligned.m8n8.x4.shared.b16 {%0,%1,%2,%3}, [%4];"
                 : "=r"(r0), "=r"(r1), "=r"(r2), "=r"(r3) : "r"(a));
}
__device__ __forceinline__ void mma16816(float* c, uint32_t a0, uint32_t a1,
                                         uint32_t a2, uint32_t a3,
                                         uint32_t b0, uint32_t b1) {
    asm volatile(
        "mma.sync.aligned.m16n8k16.row.col.f32.bf16.bf16.f32 "
        "{%0,%1,%2,%3}, {%4,%5,%6,%7}, {%8,%9}, {%0,%1,%2,%3};"
        : "+f"(c[0]), "+f"(c[1]), "+f"(c[2]), "+f"(c[3])
        : "r"(a0), "r"(a1), "r"(a2), "r"(a3), "r"(b0), "r"(b1));
}
__device__ __forceinline__ uint32_t pack_bf16x2(float x, float y) {
    __nv_bfloat16 hx = __float2bfloat16(x), hy = __float2bfloat16(y);
    return (uint32_t)*(unsigned short*)&hx | ((uint32_t)*(unsigned short*)&hy << 16);
}
__device__ __forceinline__ float sigmoid_fast(float x) {
    float e = __expf(-x);
    return __fdividef(1.f, 1.f + e);
}
__device__ __forceinline__ float tanh_fast(float x) {
    float e = __expf(-2.f * x);
    return (1.f - e) * __fdividef(1.f, 1.f + e);
}

// ---------------------------------------------------------------------------
__global__ void detect_idx_kernel(const int* __restrict__ ei32) {
    if (threadIdx.x == 0 && blockIdx.x == 0) {
        int is64 = 1;
        #pragma unroll
        for (int i = 0; i < 32; i++)
            if (ei32[2 * i + 1] != 0) { is64 = 0; break; }
        g_is64 = is64;
    }
}

// Fused: zero aggr + pack edge indices.
__global__ __launch_bounds__(256) void zero_pack_kernel(const void* __restrict__ ei,
                                                        int E, int NF4) {
    int i = blockIdx.x * blockDim.x + threadIdx.x;
    if (i < NF4)
        ((float4*)g_aggr)[i] = make_float4(0.f, 0.f, 0.f, 0.f);
    if (i < E) {
        int row, col;
        if (g_is64) {
            const long long* p = (const long long*)ei;
            row = (int)p[i]; col = (int)p[E + i];
        } else {
            const int* p = (const int*)ei;
            row = p[i]; col = p[E + i];
        }
        g_eidx[i] = make_int2(row, col);
    }
}

// prep weights: W[k][n] -> Bt[n][k] hi/lo bf16, coalesced via smem transpose.
__global__ __launch_bounds__(256) void prep_weights_kernel(
    const float* __restrict__ Wn, const float* __restrict__ Wg,
    const float* __restrict__ Wa)
{
    int mat = blockIdx.x >> 3;
    int kc  = (blockIdx.x & 7) * 16;
    const float* W = mat == 0 ? Wn : (mat == 1 ? Wg : Wa);
    __shared__ float tile[16][DIM];
    for (int i = threadIdx.x; i < 16 * DIM; i += 256) {
        int kk = i >> 7, n = i & 127;
        tile[kk][n] = W[(size_t)(kc + kk) * DIM + n];
    }
    __syncthreads();
    uint32_t* hi = (uint32_t*)g_wconv[mat][0];
    uint32_t* lo = (uint32_t*)g_wconv[mat][1];
    for (int i = threadIdx.x; i < DIM * 8; i += 256) {
        int n = i >> 3, kp = (i & 7) * 2;
        float v0 = tile[kp][n], v1 = tile[kp + 1][n];
        float h0 = __bfloat162float(__float2bfloat16(v0));
        float h1 = __bfloat162float(__float2bfloat16(v1));
        int idx = (n * DIM + kc + kp) >> 1;
        hi[idx] = pack_bf16x2(h0, h1);
        lo[idx] = pack_bf16x2(v0 - h0, v1 - h1);
    }
}

// ---------------------------------------------------------------------------
// mma.sync GEMM over nh half-K passes of 64 (K=128: nh=2).
//   mode 0: out = acc + bias
//   mode 1: out = extra * sigmoid(acc + bias)
//   mode 2: out = tanh(acc + bias + extra)
// CTA 128x128 tile, 8 warps 4(M)x2(N), SMEM 72KB -> 2 CTAs/SM.
// ---------------------------------------------------------------------------
#define KH 64
#define BSTRIDE 144
#define HBUF (DIM * BSTRIDE)           // 18432
#define SM_TOTAL (4 * HBUF)            // 73728

__global__ __launch_bounds__(256, 2) void gemm_mma_fused(
    const float* __restrict__ A0, int w0, int nh,
    const float* __restrict__ bias, const float* __restrict__ extra,
    float* __restrict__ out, int N, int mode)
{
    extern __shared__ __align__(16) char smem[];
    const uint32_t sb  = smem_u32(smem);
    const uint32_t sAH = sb, sAL = sb + HBUF, sBH = sb + 2 * HBUF, sBL = sb + 3 * HBUF;
    const int tid = threadIdx.x, lane = tid & 31, wid = tid >> 5;
    const int m0 = blockIdx.x * 128;
    const int wm = wid & 3;
    const int wn = wid >> 2;

    float acc[2][8][4];
    #pragma unroll
    for (int mt = 0; mt < 2; mt++)
        #pragma unroll
        for (int nt = 0; nt < 8; nt++)
            #pragma unroll
            for (int q = 0; q < 4; q++) acc[mt][nt][q] = 0.f;

    #pragma unroll 1
    for (int h = 0; h < nh; h++) {
        if (h) __syncthreads();

        const float* A = A0;
        const int widx = w0;
        const int kh = (h & 1);

        // A half: 128 rows x 64 cols fp32, split hi/lo bf16
        for (int i = tid; i < 128 * 16; i += 256) {
            int rl = i >> 4;
            int c4 = (i & 15) * 4;
            int r = m0 + rl; if (r >= N) r = N - 1;
            float4 v = *(const float4*)(A + (size_t)r * DIM + kh * KH + c4);
            float h0 = __bfloat162float(__float2bfloat16(v.x));
            float h1 = __bfloat162float(__float2bfloat16(v.y));
            float h2 = __bfloat162float(__float2bfloat16(v.z));
            float h3 = __bfloat162float(__float2bfloat16(v.w));
            int off = rl * BSTRIDE + c4 * 2;
            *(uint2*)(smem + off) =
                make_uint2(pack_bf16x2(h0, h1), pack_bf16x2(h2, h3));
            *(uint2*)(smem + HBUF + off) =
                make_uint2(pack_bf16x2(v.x - h0, v.y - h1),
                           pack_bf16x2(v.z - h2, v.w - h3));
        }
        // B half: pre-split Bt[n][k], 8 x 16B per row, hi and lo buffers
        {
            const char* wh = (const char*)g_wconv[widx][0];
            const char* wl = (const char*)g_wconv[widx][1];
            for (int i = tid; i < 2048; i += 256) {
                int buf = i >> 10;
                int idx = i & 1023;
                int r = idx >> 3, c = (idx & 7) * 16;
                const char* src = (buf ? wl : wh) + (size_t)r * 256 + kh * 128 + c;
                char* dst = smem + (buf ? 3 : 2) * HBUF + r * BSTRIDE + c;
                *(uint4*)dst = *(const uint4*)src;
            }
        }
        __syncthreads();

        #pragma unroll
        for (int s = 0; s < 4; s++) {
            const int k0 = s * 16;
            uint32_t ah[2][4], al[2][4];
            #pragma unroll
            for (int mt = 0; mt < 2; mt++) {
                int row = wm * 32 + mt * 16 + (lane & 15);
                int col = k0 + (lane >> 4) * 8;
                uint32_t off = row * BSTRIDE + col * 2;
                ldsm4(sAH + off, ah[mt][0], ah[mt][1], ah[mt][2], ah[mt][3]);
                ldsm4(sAL + off, al[mt][0], al[mt][1], al[mt][2], al[mt][3]);
            }
            #pragma unroll
            for (int np = 0; np < 4; np++) {
                uint32_t bh[2][2], bl[2][2];
                int g = lane >> 3;
                int row = wn * 64 + np * 16 + (g >> 1) * 8 + (lane & 7);
                int col = k0 + (g & 1) * 8;
                uint32_t off = row * BSTRIDE + col * 2;
                ldsm4(sBH + off, bh[0][0], bh[0][1], bh[1][0], bh[1][1]);
                ldsm4(sBL + off, bl[0][0], bl[0][1], bl[1][0], bl[1][1]);
                #pragma unroll
                for (int mt = 0; mt < 2; mt++)
                    #pragma unroll
                    for (int j = 0; j < 2; j++) {
                        int nt = 2 * np + j;
                        mma16816(acc[mt][nt], ah[mt][0], ah[mt][1], ah[mt][2], ah[mt][3],
                                 bh[j][0], bh[j][1]);
                        mma16816(acc[mt][nt], ah[mt][0], ah[mt][1], ah[mt][2], ah[mt][3],
                                 bl[j][0], bl[j][1]);
                        mma16816(acc[mt][nt], al[mt][0], al[mt][1], al[mt][2], al[mt][3],
                                 bh[j][0], bh[j][1]);
                    }
            }
        }
    }

    // --- Epilogue ---
    float2 bb[8];
    #pragma unroll
    for (int nt = 0; nt < 8; nt++) {
        int n = wn * 64 + nt * 8 + 2 * (lane & 3);
        bb[nt] = *(const float2*)(bias + n);
    }
    #pragma unroll
    for (int mt = 0; mt < 2; mt++) {
        #pragma unroll
        for (int half = 0; half < 2; half++) {
            int m = m0 + wm * 32 + mt * 16 + (lane >> 2) + half * 8;
            if (m >= N) continue;
            #pragma unroll
            for (int nt = 0; nt < 8; nt++) {
                int n = wn * 64 + nt * 8 + 2 * (lane & 3);
                float rx = acc[mt][nt][half * 2 + 0] + bb[nt].x;
                float ry = acc[mt][nt][half * 2 + 1] + bb[nt].y;
                if (mode == 1) {
                    float2 xv = *(const float2*)(extra + (size_t)m * DIM + n);
                    rx = xv.x * sigmoid_fast(rx);
                    ry = xv.y * sigmoid_fast(ry);
                } else if (mode == 2) {
                    float2 yv = *(const float2*)(extra + (size_t)m * DIM + n);
                    rx = tanh_fast(rx + yv.x);
                    ry = tanh_fast(ry + yv.y);
                }
                *(float2*)(out + (size_t)m * DIM + n) = make_float2(rx, ry);
            }
        }
    }
}

// ---------------------------------------------------------------------------
// Edge scatter: one warp per edge, red.global.add.v4.f32 per lane.
// ---------------------------------------------------------------------------
__global__ __launch_bounds__(256) void edge_scatter_kernel(int E)
{
    int warp = (int)((blockIdx.x * 256 + threadIdx.x) >> 5);
    if (warp >= E) return;
    int lane = threadIdx.x & 31;

    int2 rc = g_eidx[warp];
    const float* src = g_ga + (size_t)rc.y * DIM + lane * 4;
    float* dst       = g_aggr + (size_t)rc.x * DIM + lane * 4;

    float4 v = *(const float4*)src;
    asm volatile("red.global.add.v4.f32 [%0], {%1, %2, %3, %4};"
                 :: "l"(dst), "f"(v.x), "f"(v.y), "f"(v.z), "f"(v.w)
                 : "memory");
}

// ---------------------------------------------------------------------------
extern "C" void kernel_launch(void* const* d_in, const int* in_sizes, int n_in,
                              void* d_out, int out_size)
{
    const float* x    = (const float*)d_in[0];
    const void*  ei   = d_in[1];
    const float* Wn_w = (const float*)d_in[2];
    const float* Wn_b = (const float*)d_in[3];
    const float* Wg_w = (const float*)d_in[4];
    const float* Wg_b = (const float*)d_in[5];
    const float* Wa_w = (const float*)d_in[6];
    const float* Wa_b = (const float*)d_in[7];
    float* out = (float*)d_out;

    const int N = in_sizes[0] / DIM;
    const int E = in_sizes[1] / 2;

    float *p_yn, *p_ga, *p_aggr;
    cudaGetSymbolAddress((void**)&p_yn,   g_yn);
    cudaGetSymbolAddress((void**)&p_ga,   g_ga);
    cudaGetSymbolAddress((void**)&p_aggr, g_aggr);

    // Lazily-created side stream + fork/join events (infra only; no work
    // depends on call count - the captured graph is identical every call).
    static cudaStream_t s2 = nullptr;
    static cudaEvent_t ev_g = nullptr, ev_yn = nullptr;
    if (!s2) {
        cudaStreamCreateWithFlags(&s2, cudaStreamNonBlocking);
        cudaEventCreateWithFlags(&ev_g,  cudaEventDisableTiming);
        cudaEventCreateWithFlags(&ev_yn, cudaEventDisableTiming);
    }

    cudaFuncSetAttribute(gemm_mma_fused,
                         cudaFuncAttributeMaxDynamicSharedMemorySize, SM_TOTAL);

    prep_weights_kernel<<<24, 256>>>(Wn_w, Wg_w, Wa_w);
    detect_idx_kernel<<<1, 32>>>((const int*)ei);
    {
        int NF4 = N * DIM / 4;
        int total = NF4 > E ? NF4 : E;
        zero_pack_kernel<<<(total + 255) / 256, 256>>>(ei, E, NF4);
    }

    int gblocks = (N + 127) / 128;
    // g = x * sigmoid(x@Wa + ba)
    gemm_mma_fused<<<gblocks, 256, SM_TOTAL>>>(x, 2, 2, Wa_b, x, p_ga, N, 1);

    // Fork: y_n = x@Wn + bn on side stream, concurrent with the scatter.
    cudaEventRecord(ev_g, 0);
    cudaStreamWaitEvent(s2, ev_g, 0);
    gemm_mma_fused<<<gblocks, 256, SM_TOTAL, s2>>>(x, 0, 2, Wn_b, nullptr,
                                                   p_yn, N, 0);
    cudaEventRecord(ev_yn, s2);

    // Main stream: aggr[row] += g[col]
    {
        long long threads = (long long)E * 32;
        int blocks = (int)((threads + 255) / 256);
        edge_scatter_kernel<<<blocks, 256>>>(E);
    }

    // Join, then out = tanh(aggr@Wg + bg + y_n)
    cudaStreamWaitEvent(0, ev_yn, 0);
    gemm_mma_fused<<<gblocks, 256, SM_TOTAL>>>(p_aggr, 1, 2, Wg_b, p_yn,
                                               out, N, 2);
}

// round 15
// speedup vs baseline: 1.2739x; 1.0130x over previous
#include <cuda_runtime.h>
#include <cuda_bf16.h>
#include <math.h>
#include <stdint.h>

// ---------------------------------------------------------------------------
// AttentiveFPConv: out = tanh(x@Wn + bn + aggr@Wg + bg)
//   aggr[u] = sum_{e: row[e]==u} g[col[e]],  g[v] = x[v] * sigmoid((x@Wa+ba)[v])
// N = 40000, E = 640000, D = 128.
// out = tanh([x | aggr] @ [Wn ; Wg] + (bn+bg))  -- one K=256 GEMM.
// GEMMs: mma.sync m16n8k16 bf16, hi/lo split (3 terms), fp32 accum, 72KB SMEM
//        -> 2 CTAs/SM. Fast-math epilogue.
// Aggregation: warp-per-edge red.global.add.v4.f32 (LTS-bound; measured best).
// Overlap: zero/pack forked from the capture stream (event), runs under
//          prep+GEMM_g; scatter joins its event. Capture-legal fork/join only.
// ---------------------------------------------------------------------------

#define NODES_MAX 40000
#define EDGES_MAX 640000
#define DIM 128

__device__ float g_ga[NODES_MAX * DIM];
__device__ float g_aggr[NODES_MAX * DIM];
__device__ int2  g_eidx[EDGES_MAX];
__device__ float g_bsum[DIM];
__device__ __align__(16) __nv_bfloat16 g_wconv[3][2][DIM * DIM];

// ---------------------------------------------------------------------------
__device__ __forceinline__ uint32_t smem_u32(const void* p) {
    uint32_t a;
    asm("{ .reg .u64 t; cvta.to.shared.u64 t, %1; cvt.u32.u64 %0, t; }" : "=r"(a) : "l"(p));
    return a;
}
__device__ __forceinline__ void ldsm4(uint32_t a, uint32_t& r0, uint32_t& r1,
                                      uint32_t& r2, uint32_t& r3) {
    asm volatile("ldmatrix.sync.aligned.m8n8.x4.shared.b16 {%0,%1,%2,%3}, [%4];"
                 : "=r"(r0), "=r"(r1), "=r"(r2), "=r"(r3) : "r"(a));
}
__device__ __forceinline__ void mma16816(float* c, uint32_t a0, uint32_t a1,
                                         uint32_t a2, uint32_t a3,
                                         uint32_t b0, uint32_t b1) {
    asm volatile(
        "mma.sync.aligned.m16n8k16.row.col.f32.bf16.bf16.f32 "
        "{%0,%1,%2,%3}, {%4,%5,%6,%7}, {%8,%9}, {%0,%1,%2,%3};"
        : "+f"(c[0]), "+f"(c[1]), "+f"(c[2]), "+f"(c[3])
        : "r"(a0), "r"(a1), "r"(a2), "r"(a3), "r"(b0), "r"(b1));
}
__device__ __forceinline__ uint32_t pack_bf16x2(float x, float y) {
    __nv_bfloat16 hx = __float2bfloat16(x), hy = __float2bfloat16(y);
    return (uint32_t)*(unsigned short*)&hx | ((uint32_t)*(unsigned short*)&hy << 16);
}
__device__ __forceinline__ float sigmoid_fast(float x) {
    float e = __expf(-x);
    return __fdividef(1.f, 1.f + e);
}
__device__ __forceinline__ float tanh_fast(float x) {
    float e = __expf(-2.f * x);
    return (1.f - e) * __fdividef(1.f, 1.f + e);
}

// ---------------------------------------------------------------------------
// Fused: zero aggr + pack edge indices + bias sum. Index dtype (int64 vs
// int32) self-detected per thread from the first 64 words (L2-broadcast).
// ---------------------------------------------------------------------------
__global__ __launch_bounds__(256) void zero_pack_kernel(
    const void* __restrict__ ei, int E, int NF4,
    const float* __restrict__ bn, const float* __restrict__ bg)
{
    int i = blockIdx.x * blockDim.x + threadIdx.x;
    if (i < NF4)
        ((float4*)g_aggr)[i] = make_float4(0.f, 0.f, 0.f, 0.f);
    if (i < DIM)
        g_bsum[i] = bn[i] + bg[i];
    if (i < E) {
        const int* e32 = (const int*)ei;
        int is64 = 1;
        #pragma unroll
        for (int k = 0; k < 32; k++)
            if (e32[2 * k + 1] != 0) { is64 = 0; break; }
        int row, col;
        if (is64) {
            const long long* p = (const long long*)ei;
            row = (int)p[i]; col = (int)p[E + i];
        } else {
            row = e32[i]; col = e32[E + i];
        }
        g_eidx[i] = make_int2(row, col);
    }
}

// prep weights: W[k][n] -> Bt[n][k] hi/lo bf16, coalesced via smem transpose.
__global__ __launch_bounds__(256) void prep_weights_kernel(
    const float* __restrict__ Wn, const float* __restrict__ Wg,
    const float* __restrict__ Wa)
{
    int mat = blockIdx.x >> 3;
    int kc  = (blockIdx.x & 7) * 16;
    const float* W = mat == 0 ? Wn : (mat == 1 ? Wg : Wa);
    __shared__ float tile[16][DIM];
    for (int i = threadIdx.x; i < 16 * DIM; i += 256) {
        int kk = i >> 7, n = i & 127;
        tile[kk][n] = W[(size_t)(kc + kk) * DIM + n];
    }
    __syncthreads();
    uint32_t* hi = (uint32_t*)g_wconv[mat][0];
    uint32_t* lo = (uint32_t*)g_wconv[mat][1];
    for (int i = threadIdx.x; i < DIM * 8; i += 256) {
        int n = i >> 3, kp = (i & 7) * 2;
        float v0 = tile[kp][n], v1 = tile[kp + 1][n];
        float h0 = __bfloat162float(__float2bfloat16(v0));
        float h1 = __bfloat162float(__float2bfloat16(v1));
        int idx = (n * DIM + kc + kp) >> 1;
        hi[idx] = pack_bf16x2(h0, h1);
        lo[idx] = pack_bf16x2(v0 - h0, v1 - h1);
    }
}

// ---------------------------------------------------------------------------
// mma.sync GEMM over nh half-K passes of 64. Half h reads A = (h<2?A0:A1)
// at k-offset (h&1)*64, weights g_wconv[(h<2?w0:w1)].
//   mode 1: out = extra * sigmoid(acc + bias)
//   mode 3: out = tanh(acc + bias)
// CTA 128x128 tile, 8 warps 4(M)x2(N), SMEM 72KB -> 2 CTAs/SM.
// ---------------------------------------------------------------------------
#define KH 64
#define BSTRIDE 144
#define HBUF (DIM * BSTRIDE)           // 18432
#define SM_TOTAL (4 * HBUF)            // 73728

__global__ __launch_bounds__(256, 2) void gemm_mma_fused(
    const float* __restrict__ A0, const float* __restrict__ A1,
    int w0, int w1, int nh,
    const float* __restrict__ bias, const float* __restrict__ extra,
    float* __restrict__ out, int N, int mode)
{
    extern __shared__ __align__(16) char smem[];
    const uint32_t sb  = smem_u32(smem);
    const uint32_t sAH = sb, sAL = sb + HBUF, sBH = sb + 2 * HBUF, sBL = sb + 3 * HBUF;
    const int tid = threadIdx.x, lane = tid & 31, wid = tid >> 5;
    const int m0 = blockIdx.x * 128;
    const int wm = wid & 3;
    const int wn = wid >> 2;

    float acc[2][8][4];
    #pragma unroll
    for (int mt = 0; mt < 2; mt++)
        #pragma unroll
        for (int nt = 0; nt < 8; nt++)
            #pragma unroll
            for (int q = 0; q < 4; q++) acc[mt][nt][q] = 0.f;

    #pragma unroll 1
    for (int h = 0; h < nh; h++) {
        if (h) __syncthreads();

        const float* A = (h < 2) ? A0 : A1;
        const int widx = (h < 2) ? w0 : w1;
        const int kh = (h & 1);

        // A half: 128 rows x 64 cols fp32, split hi/lo bf16
        for (int i = tid; i < 128 * 16; i += 256) {
            int rl = i >> 4;
            int c4 = (i & 15) * 4;
            int r = m0 + rl; if (r >= N) r = N - 1;
            float4 v = *(const float4*)(A + (size_t)r * DIM + kh * KH + c4);
            float h0 = __bfloat162float(__float2bfloat16(v.x));
            float h1 = __bfloat162float(__float2bfloat16(v.y));
            float h2 = __bfloat162float(__float2bfloat16(v.z));
            float h3 = __bfloat162float(__float2bfloat16(v.w));
            int off = rl * BSTRIDE + c4 * 2;
            *(uint2*)(smem + off) =
                make_uint2(pack_bf16x2(h0, h1), pack_bf16x2(h2, h3));
            *(uint2*)(smem + HBUF + off) =
                make_uint2(pack_bf16x2(v.x - h0, v.y - h1),
                           pack_bf16x2(v.z - h2, v.w - h3));
        }
        // B half: pre-split Bt[n][k], 8 x 16B per row, hi and lo buffers
        {
            const char* wh = (const char*)g_wconv[widx][0];
            const char* wl = (const char*)g_wconv[widx][1];
            for (int i = tid; i < 2048; i += 256) {
                int buf = i >> 10;
                int idx = i & 1023;
                int r = idx >> 3, c = (idx & 7) * 16;
                const char* src = (buf ? wl : wh) + (size_t)r * 256 + kh * 128 + c;
                char* dst = smem + (buf ? 3 : 2) * HBUF + r * BSTRIDE + c;
                *(uint4*)dst = *(const uint4*)src;
            }
        }
        __syncthreads();

        #pragma unroll
        for (int s = 0; s < 4; s++) {
            const int k0 = s * 16;
            uint32_t ah[2][4], al[2][4];
            #pragma unroll
            for (int mt = 0; mt < 2; mt++) {
                int row = wm * 32 + mt * 16 + (lane & 15);
                int col = k0 + (lane >> 4) * 8;
                uint32_t off = row * BSTRIDE + col * 2;
                ldsm4(sAH + off, ah[mt][0], ah[mt][1], ah[mt][2], ah[mt][3]);
                ldsm4(sAL + off, al[mt][0], al[mt][1], al[mt][2], al[mt][3]);
            }
            #pragma unroll
            for (int np = 0; np < 4; np++) {
                uint32_t bh[2][2], bl[2][2];
                int g = lane >> 3;
                int row = wn * 64 + np * 16 + (g >> 1) * 8 + (lane & 7);
                int col = k0 + (g & 1) * 8;
                uint32_t off = row * BSTRIDE + col * 2;
                ldsm4(sBH + off, bh[0][0], bh[0][1], bh[1][0], bh[1][1]);
                ldsm4(sBL + off, bl[0][0], bl[0][1], bl[1][0], bl[1][1]);
                #pragma unroll
                for (int mt = 0; mt < 2; mt++)
                    #pragma unroll
                    for (int j = 0; j < 2; j++) {
                        int nt = 2 * np + j;
                        mma16816(acc[mt][nt], ah[mt][0], ah[mt][1], ah[mt][2], ah[mt][3],
                                 bh[j][0], bh[j][1]);
                        mma16816(acc[mt][nt], ah[mt][0], ah[mt][1], ah[mt][2], ah[mt][3],
                                 bl[j][0], bl[j][1]);
                        mma16816(acc[mt][nt], al[mt][0], al[mt][1], al[mt][2], al[mt][3],
                                 bh[j][0], bh[j][1]);
                    }
            }
        }
    }

    // --- Epilogue ---
    float2 bb[8];
    #pragma unroll
    for (int nt = 0; nt < 8; nt++) {
        int n = wn * 64 + nt * 8 + 2 * (lane & 3);
        bb[nt] = *(const float2*)(bias + n);
    }
    #pragma unroll
    for (int mt = 0; mt < 2; mt++) {
        #pragma unroll
        for (int half = 0; half < 2; half++) {
            int m = m0 + wm * 32 + mt * 16 + (lane >> 2) + half * 8;
            if (m >= N) continue;
            #pragma unroll
            for (int nt = 0; nt < 8; nt++) {
                int n = wn * 64 + nt * 8 + 2 * (lane & 3);
                float rx = acc[mt][nt][half * 2 + 0] + bb[nt].x;
                float ry = acc[mt][nt][half * 2 + 1] + bb[nt].y;
                if (mode == 1) {
                    float2 xv = *(const float2*)(extra + (size_t)m * DIM + n);
                    rx = xv.x * sigmoid_fast(rx);
                    ry = xv.y * sigmoid_fast(ry);
                } else {   // mode 3
                    rx = tanh_fast(rx);
                    ry = tanh_fast(ry);
                }
                *(float2*)(out + (size_t)m * DIM + n) = make_float2(rx, ry);
            }
        }
    }
}

// ---------------------------------------------------------------------------
// Edge scatter: one warp per edge, red.global.add.v4.f32 per lane.
// ---------------------------------------------------------------------------
__global__ __launch_bounds__(256) void edge_scatter_kernel(int E)
{
    int warp = (int)((blockIdx.x * 256 + threadIdx.x) >> 5);
    if (warp >= E) return;
    int lane = threadIdx.x & 31;

    int2 rc = g_eidx[warp];
    const float* src = g_ga + (size_t)rc.y * DIM + lane * 4;
    float* dst       = g_aggr + (size_t)rc.x * DIM + lane * 4;

    float4 v = *(const float4*)src;
    asm volatile("red.global.add.v4.f32 [%0], {%1, %2, %3, %4};"
                 :: "l"(dst), "f"(v.x), "f"(v.y), "f"(v.z), "f"(v.w)
                 : "memory");
}

// ---------------------------------------------------------------------------
extern "C" void kernel_launch(void* const* d_in, const int* in_sizes, int n_in,
                              void* d_out, int out_size)
{
    const float* x    = (const float*)d_in[0];
    const void*  ei   = d_in[1];
    const float* Wn_w = (const float*)d_in[2];
    const float* Wn_b = (const float*)d_in[3];
    const float* Wg_w = (const float*)d_in[4];
    const float* Wg_b = (const float*)d_in[5];
    const float* Wa_w = (const float*)d_in[6];
    const float* Wa_b = (const float*)d_in[7];
    float* out = (float*)d_out;

    const int N = in_sizes[0] / DIM;
    const int E = in_sizes[1] / 2;

    float *p_ga, *p_aggr, *p_bsum;
    cudaGetSymbolAddress((void**)&p_ga,   g_ga);
    cudaGetSymbolAddress((void**)&p_aggr, g_aggr);
    cudaGetSymbolAddress((void**)&p_bsum, g_bsum);

    static cudaStream_t s2 = nullptr;
    static cudaEvent_t ev_fork = nullptr, ev_zp = nullptr;
    if (!s2) {
        cudaStreamCreateWithFlags(&s2, cudaStreamNonBlocking);
        cudaEventCreateWithFlags(&ev_fork, cudaEventDisableTiming);
        cudaEventCreateWithFlags(&ev_zp,   cudaEventDisableTiming);
    }

    cudaFuncSetAttribute(gemm_mma_fused,
                         cudaFuncAttributeMaxDynamicSharedMemorySize, SM_TOTAL);

    // Fork s2 FROM the capture stream (required for capture legality), then
    // run zero/pack there while main does prep + GEMM_g.
    cudaEventRecord(ev_fork, 0);
    cudaStreamWaitEvent(s2, ev_fork, 0);
    {
        int NF4 = N * DIM / 4;
        int total = NF4 > E ? NF4 : E;
        zero_pack_kernel<<<(total + 255) / 256, 256, 0, s2>>>(ei, E, NF4, Wn_b, Wg_b);
    }
    cudaEventRecord(ev_zp, s2);

    // main: weight prep, then g = x * sigmoid(x@Wa + ba)
    prep_weights_kernel<<<24, 256>>>(Wn_w, Wg_w, Wa_w);
    int gblocks = (N + 127) / 128;
    gemm_mma_fused<<<gblocks, 256, SM_TOTAL>>>(x, nullptr, 2, 2, 2,
                                               Wa_b, x, p_ga, N, 1);

    // main: join zero/pack, then aggr[row] += g[col]
    cudaStreamWaitEvent(0, ev_zp, 0);
    {
        long long threads = (long long)E * 32;
        int blocks = (int)((threads + 255) / 256);
        edge_scatter_kernel<<<blocks, 256>>>(E);
    }

    // main: out = tanh([x | aggr] @ [Wn ; Wg] + bn + bg)   (K=256, 4 halves)
    gemm_mma_fused<<<gblocks, 256, SM_TOTAL>>>(x, p_aggr, 0, 1, 4,
                                               p_bsum, nullptr, out, N, 3);
}